// round 7
// baseline (speedup 1.0000x reference)
#include <cuda_runtime.h>
#include <math.h>

#define EDIM 512
#define HDIM 64
#define NH   8
#define BATCH 4
#define SEQ  2048
#define MROWS (BATCH*SEQ)   // 8192
#define FFN  2048

// ---------------- scratch (no cudaMalloc allowed) ----------------
__device__ float g_q[MROWS*EDIM];
__device__ float g_k[MROWS*EDIM];
__device__ float g_v[MROWS*EDIM];
__device__ float g_ctx[MROWS*EDIM];
__device__ float g_tmp[MROWS*EDIM];
__device__ float g_ln1[MROWS*EDIM];
__device__ float g_h[MROWS*FFN];

// ---------------- common helpers -------------------------------------------
__device__ __forceinline__ float ex2f(float x) {
    float y;
    asm("ex2.approx.ftz.f32 %0, %1;" : "=f"(y) : "f"(x));
    return y;
}
__device__ __forceinline__ void mma_tf32(float d[4],
                                         const unsigned a[4],
                                         const unsigned b[2]) {
    asm volatile(
        "mma.sync.aligned.m16n8k8.row.col.f32.tf32.tf32.f32 "
        "{%0,%1,%2,%3}, {%4,%5,%6,%7}, {%8,%9}, {%0,%1,%2,%3};\n"
        : "+f"(d[0]), "+f"(d[1]), "+f"(d[2]), "+f"(d[3])
        : "r"(a[0]), "r"(a[1]), "r"(a[2]), "r"(a[3]),
          "r"(b[0]), "r"(b[1]));
}
__device__ __forceinline__ void cp16(void* smem, const void* g) {
    unsigned s = (unsigned)__cvta_generic_to_shared(smem);
    asm volatile("cp.async.ca.shared.global [%0], [%1], 16;\n" :: "r"(s), "l"(g));
}
#define CP_COMMIT asm volatile("cp.async.commit_group;\n")
#define CP_WAIT0  asm volatile("cp.async.wait_group 0;\n")

// =================== TF32 tensor-core GEMM (cp.async 2-stage, BK=32) ========
#define GBM 128
#define GBN 128
#define GBK 32
#define GASTR 36
#define GBSTR 136
#define GEMM_SMEM ((2*GBM*GASTR + 2*GBK*GBSTR) * 4)

template<int DO_GELU>
__global__ void __launch_bounds__(256, 2) gemm_tc(
    const float* __restrict__ A, const float* __restrict__ W,
    const float* __restrict__ bias, float* __restrict__ C,
    int M, int N, int K)
{
    extern __shared__ float sm[];
    float* As = sm;
    float* Bs = sm + 2*GBM*GASTR;

    const int tid  = threadIdx.x;
    const int wid  = tid >> 5, lane = tid & 31;
    const int g    = lane >> 2, tig = lane & 3;
    const int wm   = wid >> 2,  wn  = wid & 3;
    const int bm0  = blockIdx.y * GBM, bn0 = blockIdx.x * GBN;

    const int ar = tid >> 2,  ac = (tid & 3) * 4;
    const int br = tid >> 4,  bc = (tid & 15) * 4;
    const float* Ag = A + (size_t)(bm0 + ar) * K + ac;
    const float* Wg = W + (size_t)br * N + bn0 + bc;

    float d[4][4][4] = {};
    const int nkt = K / GBK;

    cp16(&As[ar*GASTR + ac],           Ag);
    cp16(&As[ar*GASTR + ac + 16],      Ag + 16);
    cp16(&As[(ar+64)*GASTR + ac],      Ag + (size_t)64 * K);
    cp16(&As[(ar+64)*GASTR + ac + 16], Ag + (size_t)64 * K + 16);
    cp16(&Bs[br*GBSTR + bc],           Wg);
    cp16(&Bs[br*GBSTR + bc + 64],      Wg + 64);
    cp16(&Bs[(br+16)*GBSTR + bc],      Wg + (size_t)16 * N);
    cp16(&Bs[(br+16)*GBSTR + bc + 64], Wg + (size_t)16 * N + 64);
    CP_COMMIT;

    for (int kt = 0; kt < nkt; kt++) {
        const int buf = kt & 1;
        float* Ab = As + buf * (GBM*GASTR);
        float* Bb = Bs + buf * (GBK*GBSTR);
        CP_WAIT0;
        __syncthreads();

        if (kt + 1 < nkt) {
            float* An_ = As + (buf^1) * (GBM*GASTR);
            float* Bn_ = Bs + (buf^1) * (GBK*GBSTR);
            const float* Agn = Ag + (size_t)(kt+1) * GBK;
            const float* Wgn = Wg + (size_t)(kt+1) * GBK * N;
            cp16(&An_[ar*GASTR + ac],           Agn);
            cp16(&An_[ar*GASTR + ac + 16],      Agn + 16);
            cp16(&An_[(ar+64)*GASTR + ac],      Agn + (size_t)64 * K);
            cp16(&An_[(ar+64)*GASTR + ac + 16], Agn + (size_t)64 * K + 16);
            cp16(&Bn_[br*GBSTR + bc],           Wgn);
            cp16(&Bn_[br*GBSTR + bc + 64],      Wgn + 64);
            cp16(&Bn_[(br+16)*GBSTR + bc],      Wgn + (size_t)16 * N);
            cp16(&Bn_[(br+16)*GBSTR + bc + 64], Wgn + (size_t)16 * N + 64);
            CP_COMMIT;
        }

        #pragma unroll
        for (int ks = 0; ks < 4; ks++) {
            unsigned a[4][4];
            #pragma unroll
            for (int mt = 0; mt < 4; mt++) {
                const float* ap = &Ab[(wm*64 + mt*16 + g)*GASTR + ks*8 + tig];
                a[mt][0] = __float_as_uint(ap[0]);
                a[mt][1] = __float_as_uint(ap[8*GASTR]);
                a[mt][2] = __float_as_uint(ap[4]);
                a[mt][3] = __float_as_uint(ap[8*GASTR + 4]);
            }
            unsigned b[4][2];
            #pragma unroll
            for (int nt = 0; nt < 4; nt++) {
                const float* bp = &Bb[(ks*8 + tig)*GBSTR + wn*32 + nt*8 + g];
                b[nt][0] = __float_as_uint(bp[0]);
                b[nt][1] = __float_as_uint(bp[4*GBSTR]);
            }
            #pragma unroll
            for (int mt = 0; mt < 4; mt++)
                #pragma unroll
                for (int nt = 0; nt < 4; nt++)
                    mma_tf32(d[mt][nt], a[mt], b[nt]);
        }
    }

    #pragma unroll
    for (int mt = 0; mt < 4; mt++) {
        #pragma unroll
        for (int nt = 0; nt < 4; nt++) {
            const int col  = bn0 + wn*32 + nt*8 + tig*2;
            const float b0 = bias[col], b1 = bias[col + 1];
            const int row0 = bm0 + wm*64 + mt*16 + g;
            float v0 = d[mt][nt][0] + b0;
            float v1 = d[mt][nt][1] + b1;
            float v2 = d[mt][nt][2] + b0;
            float v3 = d[mt][nt][3] + b1;
            if (DO_GELU) {
                v0 = 0.5f*v0*(1.0f + erff(v0*0.70710678118654752f));
                v1 = 0.5f*v1*(1.0f + erff(v1*0.70710678118654752f));
                v2 = 0.5f*v2*(1.0f + erff(v2*0.70710678118654752f));
                v3 = 0.5f*v3*(1.0f + erff(v3*0.70710678118654752f));
            }
            *(float2*)(C + (size_t)row0 * N + col)       = make_float2(v0, v1);
            *(float2*)(C + (size_t)(row0 + 8) * N + col) = make_float2(v2, v3);
        }
    }
}

// ========== TF32 flash attention: 2D warp split (4 q-tiles x 2 key-halves) ==
// CTA: 64 query rows, 8 warps. mq = wid>>1 picks 16-row q-tile; wn = wid&1
// picks which 32 of the 64 keys this warp handles. K/V frag traffic per warp
// is halved vs the 1D split; softmax exactness kept via a per-tile SMEM
// exchange of partial row-maxes (both halves then use the same running max,
// so per-warp l and partial O combine by simple addition at the end).
#define BQ  64
#define BKV 64
#define KSTR 68   // (4g+tig) bank permutation
#define VSTR 72   // (8tig+g) bank permutation
#define PSTR 36   // (4g+tig) bank permutation
#define KBUF (BKV*KSTR)
#define VBUF (BKV*VSTR)
#define PSF  (8*16*PSTR)                    // 4608 floats
#define ATTN_SMEM ((2*KBUF + 2*VBUF + PSF + 128) * 4)   // 90624 B

__global__ void __launch_bounds__(256, 2) attn_tc(
    const float* __restrict__ Q, const float* __restrict__ K,
    const float* __restrict__ V, float* __restrict__ O)
{
    extern __shared__ float sm[];
    float* Ks = sm;
    float* Vs = sm + 2*KBUF;
    float* Ps = sm + 2*KBUF + 2*VBUF;
    float* Ex = Ps + PSF;                  // [4 mq][2 wn][16 rows]

    const int tid  = threadIdx.x;
    const int wid  = tid >> 5, lane = tid & 31;
    const int g    = lane >> 2, tig = lane & 3;
    const int mq   = wid >> 1, wn = wid & 1;
    const int qt = blockIdx.x, h = blockIdx.y, b = blockIdx.z;

    const size_t baseq  = ((size_t)(b*SEQ) + qt*BQ) * EDIM + h*HDIM;
    const size_t basekv = ((size_t)(b*SEQ)) * EDIM + h*HDIM;

    const float qscale = 0.125f * 1.4426950408889634f;
    unsigned qa[8][4];
    {
        const float* qp = Q + baseq + (size_t)(mq*16) * EDIM;
        #pragma unroll
        for (int ks = 0; ks < 8; ks++) {
            const int col = ks*8 + tig;
            qa[ks][0] = __float_as_uint(qp[(size_t)g*EDIM + col] * qscale);
            qa[ks][1] = __float_as_uint(qp[(size_t)(g+8)*EDIM + col] * qscale);
            qa[ks][2] = __float_as_uint(qp[(size_t)g*EDIM + col + 4] * qscale);
            qa[ks][3] = __float_as_uint(qp[(size_t)(g+8)*EDIM + col + 4] * qscale);
        }
    }

    float m0 = -1e30f, m1 = -1e30f, l0 = 0.f, l1 = 0.f;
    float o[8][4];
    #pragma unroll
    for (int nt = 0; nt < 8; nt++)
        #pragma unroll
        for (int j = 0; j < 4; j++) o[nt][j] = 0.f;

    float* Pw = &Ps[(wid*16) * PSTR];
    float* exMine = &Ex[(mq*2 + wn) * 16];
    float* exPeer = &Ex[(mq*2 + (wn^1)) * 16];

    const int lj = tid >> 2, lc = (tid & 3) * 4;
    const float* Kg0 = K + basekv + (size_t)lj * EDIM + lc;
    const float* Vg0 = V + basekv + (size_t)lj * EDIM + lc;
    const int nTiles = SEQ / BKV;

    #pragma unroll
    for (int i = 0; i < 4; i++) {
        cp16(&Ks[lj*KSTR + lc + i*16], Kg0 + i*16);
        cp16(&Vs[lj*VSTR + lc + i*16], Vg0 + i*16);
    }
    CP_COMMIT;

    for (int t = 0; t < nTiles; t++) {
        const int buf = t & 1;
        const float* Kb = Ks + buf * KBUF;
        const float* Vb = Vs + buf * VBUF;
        CP_WAIT0;
        __syncthreads();

        if (t + 1 < nTiles) {
            float* Kn = Ks + (buf^1) * KBUF;
            float* Vn = Vs + (buf^1) * VBUF;
            const size_t off = (size_t)(t+1) * BKV * EDIM;
            #pragma unroll
            for (int i = 0; i < 4; i++) {
                cp16(&Kn[lj*KSTR + lc + i*16], Kg0 + off + i*16);
                cp16(&Vn[lj*VSTR + lc + i*16], Vg0 + off + i*16);
            }
            CP_COMMIT;
        }

        // S = Q @ K^T for this warp's 32 keys  (m16 x n32, k=64)
        float s[4][4];
        #pragma unroll
        for (int nt = 0; nt < 4; nt++)
            #pragma unroll
            for (int j = 0; j < 4; j++) s[nt][j] = 0.f;
        #pragma unroll
        for (int ks = 0; ks < 8; ks++) {
            #pragma unroll
            for (int nt = 0; nt < 4; nt++) {
                unsigned bf[2];
                const float* bp = &Kb[(wn*32 + nt*8 + g)*KSTR + ks*8 + tig];
                bf[0] = __float_as_uint(bp[0]);
                bf[1] = __float_as_uint(bp[4]);
                mma_tf32(s[nt], qa[ks], bf);
            }
        }

        // partial row-max over this warp's 32 keys
        float rm0 = fmaxf(fmaxf(s[0][0], s[0][1]), fmaxf(s[1][0], s[1][1]));
        rm0 = fmaxf(rm0, fmaxf(fmaxf(s[2][0], s[2][1]), fmaxf(s[3][0], s[3][1])));
        float rm1 = fmaxf(fmaxf(s[0][2], s[0][3]), fmaxf(s[1][2], s[1][3]));
        rm1 = fmaxf(rm1, fmaxf(fmaxf(s[2][2], s[2][3]), fmaxf(s[3][2], s[3][3])));
        #pragma unroll
        for (int off = 1; off < 4; off <<= 1) {
            rm0 = fmaxf(rm0, __shfl_xor_sync(0xffffffffu, rm0, off));
            rm1 = fmaxf(rm1, __shfl_xor_sync(0xffffffffu, rm1, off));
        }
        // exchange with the other key-half so both use the SAME max
        if (tig == 0) { exMine[g] = rm0; exMine[g + 8] = rm1; }
        __syncthreads();
        rm0 = fmaxf(rm0, exPeer[g]);
        rm1 = fmaxf(rm1, exPeer[g + 8]);

        const float M0 = fmaxf(m0, rm0), M1 = fmaxf(m1, rm1);
        const float a0 = ex2f(m0 - M0), a1 = ex2f(m1 - M1);
        float sum0 = 0.f, sum1 = 0.f;
        #pragma unroll
        for (int nt = 0; nt < 4; nt++) {
            s[nt][0] = ex2f(s[nt][0] - M0);
            s[nt][1] = ex2f(s[nt][1] - M0);
            s[nt][2] = ex2f(s[nt][2] - M1);
            s[nt][3] = ex2f(s[nt][3] - M1);
            sum0 += s[nt][0] + s[nt][1];
            sum1 += s[nt][2] + s[nt][3];
        }
        #pragma unroll
        for (int off = 1; off < 4; off <<= 1) {
            sum0 += __shfl_xor_sync(0xffffffffu, sum0, off);
            sum1 += __shfl_xor_sync(0xffffffffu, sum1, off);
        }
        l0 = l0*a0 + sum0;  l1 = l1*a1 + sum1;   // per-warp partial l
        m0 = M0;            m1 = M1;
        #pragma unroll
        for (int nt = 0; nt < 8; nt++) {
            o[nt][0] *= a0; o[nt][1] *= a0;
            o[nt][2] *= a1; o[nt][3] *= a1;
        }

        // store P (warp-private 16x32)
        #pragma unroll
        for (int nt = 0; nt < 4; nt++) {
            *(float2*)&Pw[g*PSTR + nt*8 + 2*tig]     = make_float2(s[nt][0], s[nt][1]);
            *(float2*)&Pw[(g+8)*PSTR + nt*8 + 2*tig] = make_float2(s[nt][2], s[nt][3]);
        }
        __syncwarp();

        // O_partial += P @ V_half  (m16 x n64, k=32)
        #pragma unroll
        for (int ks = 0; ks < 4; ks++) {
            unsigned pa[4];
            const float* pp = &Pw[g*PSTR + ks*8 + tig];
            pa[0] = __float_as_uint(pp[0]);
            pa[1] = __float_as_uint(pp[8*PSTR]);
            pa[2] = __float_as_uint(pp[4]);
            pa[3] = __float_as_uint(pp[8*PSTR + 4]);
            #pragma unroll
            for (int nt = 0; nt < 8; nt++) {
                unsigned bf[2];
                const float* bp = &Vb[(wn*32 + ks*8 + tig)*VSTR + nt*8 + g];
                bf[0] = __float_as_uint(bp[0]);
                bf[1] = __float_as_uint(bp[4*VSTR]);
                mma_tf32(o[nt], pa, bf);
            }
        }
    }

    // combine the two key-halves: wn==1 publishes, wn==0 adds + stores
    __syncthreads();
    float* comb = &Ps[mq * 1024];   // 16 rows x 64 cols
    if (wn == 1) {
        #pragma unroll
        for (int nt = 0; nt < 8; nt++) {
            const int col = nt*8 + 2*tig;
            *(float2*)&comb[g*64 + col]     = make_float2(o[nt][0], o[nt][1]);
            *(float2*)&comb[(g+8)*64 + col] = make_float2(o[nt][2], o[nt][3]);
        }
        if (tig == 0) { Ex[mq*16 + g] = l0; Ex[mq*16 + g + 8] = l1; }
    }
    __syncthreads();
    if (wn == 0) {
        const float inv0 = 1.0f / (l0 + Ex[mq*16 + g]);
        const float inv1 = 1.0f / (l1 + Ex[mq*16 + g + 8]);
        float* Og = (float*)(O + baseq + (size_t)(mq*16) * EDIM);
        #pragma unroll
        for (int nt = 0; nt < 8; nt++) {
            const int col = nt*8 + 2*tig;
            float2 p0 = *(float2*)&comb[g*64 + col];
            float2 p1 = *(float2*)&comb[(g+8)*64 + col];
            *(float2*)(Og + (size_t)g*EDIM + col) =
                make_float2((o[nt][0] + p0.x)*inv0, (o[nt][1] + p0.y)*inv0);
            *(float2*)(Og + (size_t)(g+8)*EDIM + col) =
                make_float2((o[nt][2] + p1.x)*inv1, (o[nt][3] + p1.y)*inv1);
        }
    }
}

// ---------------- fused residual + LayerNorm (warp per row) -----------------
__global__ void __launch_bounds__(256) ln_kernel(
    const float* __restrict__ X, const float* __restrict__ Y,
    const float* __restrict__ gamma, const float* __restrict__ beta,
    float* __restrict__ out)
{
    const int lane = threadIdx.x & 31;
    const int row  = blockIdx.x * 8 + (threadIdx.x >> 5);

    float4 v[4];
    float sum = 0.f, sq = 0.f;
    #pragma unroll
    for (int i = 0; i < 4; i++) {
        const int c = (i*32 + lane) * 4;
        float4 xv = *(const float4*)(X + (size_t)row*EDIM + c);
        float4 yv = *(const float4*)(Y + (size_t)row*EDIM + c);
        v[i].x = xv.x + yv.x; v[i].y = xv.y + yv.y;
        v[i].z = xv.z + yv.z; v[i].w = xv.w + yv.w;
        sum += v[i].x + v[i].y + v[i].z + v[i].w;
        sq  += v[i].x*v[i].x + v[i].y*v[i].y + v[i].z*v[i].z + v[i].w*v[i].w;
    }
    #pragma unroll
    for (int off = 16; off > 0; off >>= 1) {
        sum += __shfl_xor_sync(0xffffffffu, sum, off);
        sq  += __shfl_xor_sync(0xffffffffu, sq, off);
    }
    const float mu   = sum * (1.0f/EDIM);
    const float var  = sq * (1.0f/EDIM) - mu*mu;
    const float rstd = rsqrtf(var + 1e-5f);

    #pragma unroll
    for (int i = 0; i < 4; i++) {
        const int c = (i*32 + lane) * 4;
        float4 gv = *(const float4*)(gamma + c);
        float4 bv = *(const float4*)(beta  + c);
        float4 ov;
        ov.x = (v[i].x - mu)*rstd*gv.x + bv.x;
        ov.y = (v[i].y - mu)*rstd*gv.y + bv.y;
        ov.z = (v[i].z - mu)*rstd*gv.z + bv.z;
        ov.w = (v[i].w - mu)*rstd*gv.w + bv.w;
        *(float4*)(out + (size_t)row*EDIM + c) = ov;
    }
}

// ---------------- launch ----------------------------------------------------
extern "C" void kernel_launch(void* const* d_in, const int* in_sizes, int n_in,
                              void* d_out, int out_size)
{
    const float* query = (const float*)d_in[0];
    const float* key   = (const float*)d_in[1];
    const float* value = (const float*)d_in[2];
    const float* Wq = (const float*)d_in[3];  const float* bq = (const float*)d_in[4];
    const float* Wk = (const float*)d_in[5];  const float* bk = (const float*)d_in[6];
    const float* Wv = (const float*)d_in[7];  const float* bv = (const float*)d_in[8];
    const float* Wo = (const float*)d_in[9];  const float* bo = (const float*)d_in[10];
    const float* g1 = (const float*)d_in[11]; const float* be1 = (const float*)d_in[12];
    const float* g2 = (const float*)d_in[13]; const float* be2 = (const float*)d_in[14];
    const float* W1 = (const float*)d_in[15]; const float* b1 = (const float*)d_in[16];
    const float* W2 = (const float*)d_in[17]; const float* b2 = (const float*)d_in[18];
    float* out = (float*)d_out;

    float *q, *k, *v, *ctx, *tmp, *ln1, *hbuf;
    cudaGetSymbolAddress((void**)&q,    g_q);
    cudaGetSymbolAddress((void**)&k,    g_k);
    cudaGetSymbolAddress((void**)&v,    g_v);
    cudaGetSymbolAddress((void**)&ctx,  g_ctx);
    cudaGetSymbolAddress((void**)&tmp,  g_tmp);
    cudaGetSymbolAddress((void**)&ln1,  g_ln1);
    cudaGetSymbolAddress((void**)&hbuf, g_h);

    cudaFuncSetAttribute(gemm_tc<0>, cudaFuncAttributeMaxDynamicSharedMemorySize, GEMM_SMEM);
    cudaFuncSetAttribute(gemm_tc<1>, cudaFuncAttributeMaxDynamicSharedMemorySize, GEMM_SMEM);
    cudaFuncSetAttribute(attn_tc,    cudaFuncAttributeMaxDynamicSharedMemorySize, ATTN_SMEM);

    dim3 gProj(EDIM/GBN, MROWS/GBM);   // 4 x 64
    dim3 gF1(FFN/GBN,  MROWS/GBM);     // 16 x 64

    gemm_tc<0><<<gProj, 256, GEMM_SMEM>>>(query, Wq, bq, q, MROWS, EDIM, EDIM);
    gemm_tc<0><<<gProj, 256, GEMM_SMEM>>>(key,   Wk, bk, k, MROWS, EDIM, EDIM);
    gemm_tc<0><<<gProj, 256, GEMM_SMEM>>>(value, Wv, bv, v, MROWS, EDIM, EDIM);

    attn_tc<<<dim3(SEQ/BQ, NH, BATCH), 256, ATTN_SMEM>>>(q, k, v, ctx);

    gemm_tc<0><<<gProj, 256, GEMM_SMEM>>>(ctx, Wo, bo, tmp, MROWS, EDIM, EDIM);
    ln_kernel<<<MROWS/8, 256>>>(query, tmp, g1, be1, ln1);

    gemm_tc<1><<<gF1, 256, GEMM_SMEM>>>(ln1, W1, b1, hbuf, MROWS, FFN, EDIM);
    gemm_tc<0><<<gProj, 256, GEMM_SMEM>>>(hbuf, W2, b2, tmp, MROWS, EDIM, FFN);
    ln_kernel<<<MROWS/8, 256>>>(ln1, tmp, g2, be2, out);
}